// round 2
// baseline (speedup 1.0000x reference)
#include <cuda_runtime.h>
#include <math.h>
#include <stdint.h>

// Problem constants
#define TOK   2048
#define DIM   256
#define HDIM  64
#define NH    4
#define NB    4
#define MTOK  8192        // NB*TOK
#define BH    16          // NB*NH

// ---------------- scratch (device globals; no allocation allowed) ----------------
__device__ float g_qk0[MTOK * DIM];
__device__ float g_qk1[MTOK * DIM];
__device__ float g_v0 [MTOK * DIM];
__device__ float g_v1 [MTOK * DIM];
__device__ float g_m0 [MTOK * DIM];
__device__ float g_m1 [MTOK * DIM];
__device__ float g_mp0[MTOK * DIM];
__device__ float g_mp1[MTOK * DIM];
__device__ float g_y0 [MTOK * 512];
__device__ float g_y1 [MTOK * 512];
__device__ float g_E  [(size_t)BH * TOK * TOK];   // exp(logits), 256 MB
__device__ float g_rs [BH * TOK];                 // 1 / row sums
__device__ float g_cs [BH * TOK];                 // 1 / col sums

// ---------------- fast exp on the FMA pipe (avoids MUFU bottleneck) ----------------
__device__ __forceinline__ float fast_exp(float x) {
    float t = x * 1.4426950408889634f;   // x * log2(e)
    float r = rintf(t);
    float f = t - r;
    // 2^f on [-0.5, 0.5], degree-6 Taylor (rel err < 3e-7)
    float p = 1.5403530e-4f;
    p = fmaf(p, f, 1.3333558e-3f);
    p = fmaf(p, f, 9.6181291e-3f);
    p = fmaf(p, f, 5.5504109e-2f);
    p = fmaf(p, f, 2.4022651e-1f);
    p = fmaf(p, f, 6.9314718e-1f);
    p = fmaf(p, f, 1.0f);
    int e = (int)r;
    return __int_as_float(__float_as_int(p) + (e << 23));
}

// ---------------- generic tiled fp32 GEMM core: C = A @ W + bias (+res) ----------------
// BM=BN=64, BK=16, 256 threads, 4x4 per thread. Smem [k][x], pad 68.
template<bool CONCAT, bool RES>
__device__ __forceinline__
void gemm_core(const float* __restrict__ A, const float* __restrict__ A2,
               const float* __restrict__ W, const float* __restrict__ bias,
               const float* __restrict__ res, float* __restrict__ C,
               int N, int K)
{
    __shared__ float Ast[16][68];
    __shared__ float Wst[16][68];
    const int row0 = blockIdx.x * 64;
    const int col0 = blockIdx.y * 64;
    const int tid  = threadIdx.x;
    const int ty   = tid >> 4, tx = tid & 15;

    float acc[4][4] = {};

    for (int k0 = 0; k0 < K; k0 += 16) {
        #pragma unroll
        for (int e = tid; e < 1024; e += 256) {
            int r = e >> 4, c = e & 15;
            int kk = k0 + c;
            float v;
            if (CONCAT) {
                v = (kk < 256) ? A [(size_t)(row0 + r) * 256 + kk]
                               : A2[(size_t)(row0 + r) * 256 + (kk - 256)];
            } else {
                v = A[(size_t)(row0 + r) * K + kk];
            }
            Ast[c][r] = v;
        }
        #pragma unroll
        for (int e = tid; e < 1024; e += 256) {
            int kk = e >> 6, n = e & 63;
            Wst[kk][n] = W[(size_t)(k0 + kk) * N + col0 + n];
        }
        __syncthreads();
        #pragma unroll
        for (int kk = 0; kk < 16; kk++) {
            float4 a4 = *(const float4*)&Ast[kk][ty * 4];
            float4 b4 = *(const float4*)&Wst[kk][tx * 4];
            float av[4] = {a4.x, a4.y, a4.z, a4.w};
            float bv[4] = {b4.x, b4.y, b4.z, b4.w};
            #pragma unroll
            for (int i = 0; i < 4; i++)
                #pragma unroll
                for (int j = 0; j < 4; j++)
                    acc[i][j] = fmaf(av[i], bv[j], acc[i][j]);
        }
        __syncthreads();
    }

    #pragma unroll
    for (int i = 0; i < 4; i++) {
        int r = row0 + ty * 4 + i;
        #pragma unroll
        for (int j = 0; j < 4; j++) {
            int c = col0 + tx * 4 + j;
            float v = acc[i][j] + bias[c];
            if (RES) v += res[(size_t)r * N + c];
            C[(size_t)r * N + c] = v;
        }
    }
}

// ---- merged launch wrappers (blockIdx.z selects the sub-problem) ----
__global__ __launch_bounds__(256)
void proj_kernel(const float* __restrict__ x0, const float* __restrict__ x1,
                 const float* __restrict__ Wqk, const float* __restrict__ bqk,
                 const float* __restrict__ Wv,  const float* __restrict__ bv,
                 float* __restrict__ qk0, float* __restrict__ qk1,
                 float* __restrict__ v0,  float* __restrict__ v1)
{
    const int z = blockIdx.z;
    const float* A = (z & 1) ? x1 : x0;
    const float* W = (z < 2) ? Wqk : Wv;
    const float* b = (z < 2) ? bqk : bv;
    float* C = (z == 0) ? qk0 : (z == 1) ? qk1 : (z == 2) ? v0 : v1;
    gemm_core<false, false>(A, nullptr, W, b, nullptr, C, DIM, DIM);
}

__global__ __launch_bounds__(256)
void wout_kernel(const float* __restrict__ m0, const float* __restrict__ m1,
                 const float* __restrict__ Wout, const float* __restrict__ bout,
                 float* __restrict__ mp0, float* __restrict__ mp1)
{
    const int z = blockIdx.z;
    gemm_core<false, false>(z ? m1 : m0, nullptr, Wout, bout, nullptr,
                            z ? mp1 : mp0, DIM, DIM);
}

__global__ __launch_bounds__(256)
void ffn1_kernel(const float* __restrict__ x0, const float* __restrict__ x1,
                 const float* __restrict__ mp0, const float* __restrict__ mp1,
                 const float* __restrict__ W0, const float* __restrict__ b0,
                 float* __restrict__ y0, float* __restrict__ y1)
{
    const int z = blockIdx.z;
    gemm_core<true, false>(z ? x1 : x0, z ? mp1 : mp0, W0, b0, nullptr,
                           z ? y1 : y0, 512, 512);
}

__global__ __launch_bounds__(256)
void ffn2_kernel(const float* __restrict__ y0, const float* __restrict__ y1,
                 const float* __restrict__ W3, const float* __restrict__ b3,
                 const float* __restrict__ x0, const float* __restrict__ x1,
                 float* __restrict__ out0, float* __restrict__ out1)
{
    const int z = blockIdx.z;
    gemm_core<false, true>(z ? y1 : y0, nullptr, W3, b3, z ? x1 : x0,
                           z ? out1 : out0, DIM, 512);
}

// ---------------- logits (NT GEMM, K=64) + fused exp -> E ----------------
__global__ __launch_bounds__(256)
void logits_exp(const float* __restrict__ qk0, const float* __restrict__ qk1,
                float* __restrict__ E)
{
    __shared__ float Ast[64][68];   // [k][i]
    __shared__ float Bst[64][68];   // [k][j]
    const int i0 = blockIdx.x * 64;
    const int j0 = blockIdx.y * 64;
    const int bh = blockIdx.z;
    const int b  = bh >> 2, h = bh & 3;
    const float* A  = qk0 + (size_t)b * TOK * DIM + h * HDIM;
    const float* Bp = qk1 + (size_t)b * TOK * DIM + h * HDIM;
    float* Eb = E + (size_t)bh * TOK * TOK;
    const int tid = threadIdx.x, ty = tid >> 4, tx = tid & 15;

    for (int e = tid; e < 4096; e += 256) {
        int r = e >> 6, c = e & 63;
        Ast[c][r] = A [(size_t)(i0 + r) * DIM + c];
        Bst[c][r] = Bp[(size_t)(j0 + r) * DIM + c];
    }
    __syncthreads();

    float acc[4][4] = {};
    #pragma unroll 16
    for (int k = 0; k < 64; k++) {
        float4 a4 = *(const float4*)&Ast[k][ty * 4];
        float4 b4 = *(const float4*)&Bst[k][tx * 4];
        float av[4] = {a4.x, a4.y, a4.z, a4.w};
        float bv[4] = {b4.x, b4.y, b4.z, b4.w};
        #pragma unroll
        for (int i = 0; i < 4; i++)
            #pragma unroll
            for (int j = 0; j < 4; j++)
                acc[i][j] = fmaf(av[i], bv[j], acc[i][j]);
    }

    const float scale = 0.125f;   // 1/sqrt(64)
    #pragma unroll
    for (int i = 0; i < 4; i++) {
        int gi = i0 + ty * 4 + i;
        #pragma unroll
        for (int j = 0; j < 4; j++) {
            int gj = j0 + tx * 4 + j;
            Eb[(size_t)gi * TOK + gj] = fast_exp(acc[i][j] * scale);
        }
    }
}

// ---------------- row sums (1/sum over j) ----------------
__global__ __launch_bounds__(256)
void rowsum_inv(const float* __restrict__ E, float* __restrict__ rs)
{
    const int bh = blockIdx.y;
    const int i  = blockIdx.x;
    const float4* row4 = (const float4*)(E + (size_t)bh * TOK * TOK + (size_t)i * TOK);
    float s = 0.f;
    for (int j = threadIdx.x; j < TOK / 4; j += 256) {
        float4 v = row4[j];
        s += (v.x + v.y) + (v.z + v.w);
    }
    __shared__ float red[256];
    red[threadIdx.x] = s;
    __syncthreads();
    for (int off = 128; off > 0; off >>= 1) {
        if (threadIdx.x < off) red[threadIdx.x] += red[threadIdx.x + off];
        __syncthreads();
    }
    if (threadIdx.x == 0) rs[bh * TOK + i] = 1.0f / red[0];
}

// ---------------- col sums (1/sum over i) ----------------
__global__ __launch_bounds__(256)
void colsum_inv(const float* __restrict__ E, float* __restrict__ cs)
{
    const int bh = blockIdx.y;
    const int c  = blockIdx.x * 256 + threadIdx.x;
    const float* Eb = E + (size_t)bh * TOK * TOK;
    float s0 = 0.f, s1 = 0.f, s2 = 0.f, s3 = 0.f;
    float s4 = 0.f, s5 = 0.f, s6 = 0.f, s7 = 0.f;
    for (int j = 0; j < TOK; j += 8) {
        s0 += Eb[(size_t)(j + 0) * TOK + c];
        s1 += Eb[(size_t)(j + 1) * TOK + c];
        s2 += Eb[(size_t)(j + 2) * TOK + c];
        s3 += Eb[(size_t)(j + 3) * TOK + c];
        s4 += Eb[(size_t)(j + 4) * TOK + c];
        s5 += Eb[(size_t)(j + 5) * TOK + c];
        s6 += Eb[(size_t)(j + 6) * TOK + c];
        s7 += Eb[(size_t)(j + 7) * TOK + c];
    }
    cs[bh * TOK + c] = 1.0f / (((s0 + s1) + (s2 + s3)) + ((s4 + s5) + (s6 + s7)));
}

// ---------------- merged: m0 = (E @ v1)*rs  (z=0) | m1 = (E^T @ v0)*cs (z=1) ----------------
__global__ __launch_bounds__(256)
void apply_both(const float* __restrict__ E,
                const float* __restrict__ v0g, const float* __restrict__ v1g,
                const float* __restrict__ rs,  const float* __restrict__ cs,
                float* __restrict__ m0g, float* __restrict__ m1g)
{
    __shared__ float Pst[64][68];
    __shared__ float Vst[64][68];
    const int mode = blockIdx.z;            // 0 = row-softmax (m0), 1 = col-softmax (m1)
    const int i0 = blockIdx.x * 64;
    const int bh = blockIdx.y;
    const int b  = bh >> 2, h = bh & 3;
    const float* Eb  = E + (size_t)bh * TOK * TOK;
    const float* Vb  = (mode ? v0g : v1g) + (size_t)b * TOK * DIM + h * HDIM;
    const float* inv = (mode ? cs : rs) + bh * TOK;
    float* Mout      = (mode ? m1g : m0g);
    const int tid = threadIdx.x, ty = tid >> 4, tx = tid & 15;

    float acc[4][4] = {};
    for (int j0 = 0; j0 < TOK; j0 += 64) {
        for (int e = tid; e < 4096; e += 256) {
            int r = e >> 6, c = e & 63;
            if (mode == 0)
                Pst[c][r] = Eb[(size_t)(i0 + r) * TOK + j0 + c];
            else
                Pst[r][c] = Eb[(size_t)(j0 + r) * TOK + i0 + c];
            Vst[r][c] = Vb[(size_t)(j0 + r) * DIM + c];
        }
        __syncthreads();
        #pragma unroll 16
        for (int k = 0; k < 64; k++) {
            float4 a4 = *(const float4*)&Pst[k][ty * 4];
            float4 b4 = *(const float4*)&Vst[k][tx * 4];
            float av[4] = {a4.x, a4.y, a4.z, a4.w};
            float bv[4] = {b4.x, b4.y, b4.z, b4.w};
            #pragma unroll
            for (int i = 0; i < 4; i++)
                #pragma unroll
                for (int j = 0; j < 4; j++)
                    acc[i][j] = fmaf(av[i], bv[j], acc[i][j]);
        }
        __syncthreads();
    }
    #pragma unroll
    for (int i = 0; i < 4; i++) {
        int gi = i0 + ty * 4 + i;
        float s = inv[gi];
        #pragma unroll
        for (int j = 0; j < 4; j++)
            Mout[(size_t)(b * TOK + gi) * DIM + h * HDIM + tx * 4 + j] = acc[i][j] * s;
    }
}

// ---------------- fused LayerNorm + exact GELU, in-place on [rows, 512] ----------------
__global__ __launch_bounds__(256)
void ln_gelu(float* __restrict__ Y0, float* __restrict__ Y1,
             const float* __restrict__ gam, const float* __restrict__ bet)
{
    const int row = blockIdx.x;
    float* y = (blockIdx.y ? Y1 : Y0) + (size_t)row * 512;
    const int t = threadIdx.x;

    float v0 = y[t], v1 = y[t + 256];

    __shared__ float red[256];
    red[t] = v0 + v1;
    __syncthreads();
    for (int off = 128; off > 0; off >>= 1) {
        if (t < off) red[t] += red[t + off];
        __syncthreads();
    }
    float mu = red[0] * (1.0f / 512.0f);
    __syncthreads();

    float d0 = v0 - mu, d1 = v1 - mu;
    red[t] = d0 * d0 + d1 * d1;
    __syncthreads();
    for (int off = 128; off > 0; off >>= 1) {
        if (t < off) red[t] += red[t + off];
        __syncthreads();
    }
    float inv = rsqrtf(red[0] * (1.0f / 512.0f) + 1e-5f);

    float z0 = d0 * inv * gam[t] + bet[t];
    float z1 = d1 * inv * gam[t + 256] + bet[t + 256];
    y[t]       = 0.5f * z0 * (1.0f + erff(z0 * 0.70710678118654752f));
    y[t + 256] = 0.5f * z1 * (1.0f + erff(z1 * 0.70710678118654752f));
}

// ---------------- launch ----------------
extern "C" void kernel_launch(void* const* d_in, const int* in_sizes, int n_in,
                              void* d_out, int out_size)
{
    const float* x0   = (const float*)d_in[0];
    const float* x1   = (const float*)d_in[1];
    const float* Wqk  = (const float*)d_in[2];
    const float* bqk  = (const float*)d_in[3];
    const float* Wv   = (const float*)d_in[4];
    const float* bv   = (const float*)d_in[5];
    const float* Wout = (const float*)d_in[6];
    const float* bout = (const float*)d_in[7];
    const float* W0   = (const float*)d_in[8];
    const float* b0   = (const float*)d_in[9];
    const float* lns  = (const float*)d_in[10];
    const float* lnb  = (const float*)d_in[11];
    const float* W3   = (const float*)d_in[12];
    const float* b3   = (const float*)d_in[13];

    float* out0 = (float*)d_out;
    float* out1 = (float*)d_out + (size_t)MTOK * DIM;

    float *qk0, *qk1, *v0, *v1, *m0, *m1, *mp0, *mp1, *y0, *y1, *E, *rs, *cs;
    cudaGetSymbolAddress((void**)&qk0, g_qk0);
    cudaGetSymbolAddress((void**)&qk1, g_qk1);
    cudaGetSymbolAddress((void**)&v0,  g_v0);
    cudaGetSymbolAddress((void**)&v1,  g_v1);
    cudaGetSymbolAddress((void**)&m0,  g_m0);
    cudaGetSymbolAddress((void**)&m1,  g_m1);
    cudaGetSymbolAddress((void**)&mp0, g_mp0);
    cudaGetSymbolAddress((void**)&mp1, g_mp1);
    cudaGetSymbolAddress((void**)&y0,  g_y0);
    cudaGetSymbolAddress((void**)&y1,  g_y1);
    cudaGetSymbolAddress((void**)&E,   g_E);
    cudaGetSymbolAddress((void**)&rs,  g_rs);
    cudaGetSymbolAddress((void**)&cs,  g_cs);

    dim3 thr(256);

    // projections: 4 x [8192,256]@[256,256] in one launch (z selects)
    proj_kernel<<<dim3(MTOK / 64, DIM / 64, 4), thr>>>(
        x0, x1, Wqk, bqk, Wv, bv, qk0, qk1, v0, v1);

    // E = exp(scale * qk0 @ qk1^T) per (b,h)
    logits_exp<<<dim3(TOK / 64, TOK / 64, BH), thr>>>(qk0, qk1, E);

    rowsum_inv<<<dim3(TOK, BH), thr>>>(E, rs);
    colsum_inv<<<dim3(TOK / 256, BH), thr>>>(E, cs);

    // both attention applies in one launch
    apply_both<<<dim3(TOK / 64, BH, 2), thr>>>(E, v0, v1, rs, cs, m0, m1);

    // out projection (both streams)
    wout_kernel<<<dim3(MTOK / 64, DIM / 64, 2), thr>>>(m0, m1, Wout, bout, mp0, mp1);

    // FFN1: [x | m] @ W0 + b0 -> [8192, 512] (both streams)
    ffn1_kernel<<<dim3(MTOK / 64, 512 / 64, 2), thr>>>(x0, x1, mp0, mp1, W0, b0, y0, y1);

    // LN + GELU in place (both streams)
    ln_gelu<<<dim3(MTOK, 2), thr>>>(y0, y1, lns, lnb);

    // FFN2 + residual (both streams)
    ffn2_kernel<<<dim3(MTOK / 64, DIM / 64, 2), thr>>>(y0, y1, W3, b3, x0, x1, out0, out1);
}

// round 3
// speedup vs baseline: 1.0479x; 1.0479x over previous
#include <cuda_runtime.h>
#include <math.h>
#include <stdint.h>

// Problem constants
#define TOK   2048
#define DIM   256
#define HDIM  64
#define NH    4
#define NB    4
#define MTOK  8192        // NB*TOK
#define BH    16          // NB*NH

// ---------------- scratch (device globals; no allocation allowed) ----------------
__device__ float g_qk0[MTOK * DIM];
__device__ float g_qk1[MTOK * DIM];
__device__ float g_v0 [MTOK * DIM];
__device__ float g_v1 [MTOK * DIM];
__device__ float g_m0 [MTOK * DIM];
__device__ float g_m1 [MTOK * DIM];
__device__ float g_mp0[MTOK * DIM];
__device__ float g_mp1[MTOK * DIM];
__device__ float g_y0 [MTOK * 512];
__device__ float g_y1 [MTOK * 512];
__device__ float g_E  [(size_t)BH * TOK * TOK];   // exp(logits), 256 MB
__device__ float g_rs [BH * TOK];                 // row sums (exp)
__device__ float g_cs [BH * TOK];                 // col sums (exp)

// ---------------- fast exp on the FMA pipe (avoids MUFU bottleneck) ----------------
__device__ __forceinline__ float fast_exp(float x) {
    float t = x * 1.4426950408889634f;   // x * log2(e)
    float r = rintf(t);
    float f = t - r;
    float p = 1.5403530e-4f;
    p = fmaf(p, f, 1.3333558e-3f);
    p = fmaf(p, f, 9.6181291e-3f);
    p = fmaf(p, f, 5.5504109e-2f);
    p = fmaf(p, f, 2.4022651e-1f);
    p = fmaf(p, f, 6.9314718e-1f);
    p = fmaf(p, f, 1.0f);
    int e = (int)r;
    return __int_as_float(__float_as_int(p) + (e << 23));
}

// ---------------- zero the sum accumulators (graph-replay safe) ----------------
__global__ __launch_bounds__(512)
void zero_sums(float* __restrict__ rs, float* __restrict__ cs)
{
    int i = blockIdx.x * 512 + threadIdx.x;
    if (i < BH * TOK) { rs[i] = 0.f; cs[i] = 0.f; }
}

// ---------------- generic tiled fp32 GEMM core: C = A @ W + bias (+res) ----------------
// BM=BN=64, BK=16, 256 threads, 4x4 per thread. Smem [k][x], pad 68.
template<bool CONCAT, bool RES>
__device__ __forceinline__
void gemm_core(const float* __restrict__ A, const float* __restrict__ A2,
               const float* __restrict__ W, const float* __restrict__ bias,
               const float* __restrict__ res, float* __restrict__ C,
               int N, int K)
{
    __shared__ float Ast[16][68];
    __shared__ float Wst[16][68];
    const int row0 = blockIdx.x * 64;
    const int col0 = blockIdx.y * 64;
    const int tid  = threadIdx.x;
    const int ty   = tid >> 4, tx = tid & 15;

    float acc[4][4] = {};

    for (int k0 = 0; k0 < K; k0 += 16) {
        #pragma unroll
        for (int e = tid; e < 1024; e += 256) {
            int r = e >> 4, c = e & 15;
            int kk = k0 + c;
            float v;
            if (CONCAT) {
                v = (kk < 256) ? A [(size_t)(row0 + r) * 256 + kk]
                               : A2[(size_t)(row0 + r) * 256 + (kk - 256)];
            } else {
                v = A[(size_t)(row0 + r) * K + kk];
            }
            Ast[c][r] = v;
        }
        #pragma unroll
        for (int e = tid; e < 1024; e += 256) {
            int kk = e >> 6, n = e & 63;
            Wst[kk][n] = W[(size_t)(k0 + kk) * N + col0 + n];
        }
        __syncthreads();
        #pragma unroll
        for (int kk = 0; kk < 16; kk++) {
            float4 a4 = *(const float4*)&Ast[kk][ty * 4];
            float4 b4 = *(const float4*)&Wst[kk][tx * 4];
            float av[4] = {a4.x, a4.y, a4.z, a4.w};
            float bv[4] = {b4.x, b4.y, b4.z, b4.w};
            #pragma unroll
            for (int i = 0; i < 4; i++)
                #pragma unroll
                for (int j = 0; j < 4; j++)
                    acc[i][j] = fmaf(av[i], bv[j], acc[i][j]);
        }
        __syncthreads();
    }

    #pragma unroll
    for (int i = 0; i < 4; i++) {
        int r = row0 + ty * 4 + i;
        #pragma unroll
        for (int j = 0; j < 4; j++) {
            int c = col0 + tx * 4 + j;
            float v = acc[i][j] + bias[c];
            if (RES) v += res[(size_t)r * N + c];
            C[(size_t)r * N + c] = v;
        }
    }
}

// ---- merged launch wrappers (blockIdx.z selects the sub-problem) ----
__global__ __launch_bounds__(256)
void proj_kernel(const float* __restrict__ x0, const float* __restrict__ x1,
                 const float* __restrict__ Wqk, const float* __restrict__ bqk,
                 const float* __restrict__ Wv,  const float* __restrict__ bv,
                 float* __restrict__ qk0, float* __restrict__ qk1,
                 float* __restrict__ v0,  float* __restrict__ v1)
{
    const int z = blockIdx.z;
    const float* A = (z & 1) ? x1 : x0;
    const float* W = (z < 2) ? Wqk : Wv;
    const float* b = (z < 2) ? bqk : bv;
    float* C = (z == 0) ? qk0 : (z == 1) ? qk1 : (z == 2) ? v0 : v1;
    gemm_core<false, false>(A, nullptr, W, b, nullptr, C, DIM, DIM);
}

__global__ __launch_bounds__(256)
void wout_kernel(const float* __restrict__ m0, const float* __restrict__ m1,
                 const float* __restrict__ Wout, const float* __restrict__ bout,
                 float* __restrict__ mp0, float* __restrict__ mp1)
{
    const int z = blockIdx.z;
    gemm_core<false, false>(z ? m1 : m0, nullptr, Wout, bout, nullptr,
                            z ? mp1 : mp0, DIM, DIM);
}

__global__ __launch_bounds__(256)
void ffn1_kernel(const float* __restrict__ x0, const float* __restrict__ x1,
                 const float* __restrict__ mp0, const float* __restrict__ mp1,
                 const float* __restrict__ W0, const float* __restrict__ b0,
                 float* __restrict__ y0, float* __restrict__ y1)
{
    const int z = blockIdx.z;
    gemm_core<true, false>(z ? x1 : x0, z ? mp1 : mp0, W0, b0, nullptr,
                           z ? y1 : y0, 512, 512);
}

__global__ __launch_bounds__(256)
void ffn2_kernel(const float* __restrict__ y0, const float* __restrict__ y1,
                 const float* __restrict__ W3, const float* __restrict__ b3,
                 const float* __restrict__ x0, const float* __restrict__ x1,
                 float* __restrict__ out0, float* __restrict__ out1)
{
    const int z = blockIdx.z;
    gemm_core<false, true>(z ? y1 : y0, nullptr, W3, b3, z ? x1 : x0,
                           z ? out1 : out0, DIM, 512);
}

// ---------------- logits (NT GEMM, K=64) + fused exp -> E, + fused row/col sums ----------------
__global__ __launch_bounds__(256)
void logits_exp(const float* __restrict__ qk0, const float* __restrict__ qk1,
                float* __restrict__ E, float* __restrict__ rs, float* __restrict__ cs)
{
    __shared__ float Ast[64][68];   // [k][i]
    __shared__ float Bst[64][68];   // [k][j]
    const int i0 = blockIdx.x * 64;
    const int j0 = blockIdx.y * 64;
    const int bh = blockIdx.z;
    const int b  = bh >> 2, h = bh & 3;
    const float* A  = qk0 + (size_t)b * TOK * DIM + h * HDIM;
    const float* Bp = qk1 + (size_t)b * TOK * DIM + h * HDIM;
    float* Eb = E + (size_t)bh * TOK * TOK;
    const int tid = threadIdx.x, ty = tid >> 4, tx = tid & 15;

    for (int e = tid; e < 4096; e += 256) {
        int r = e >> 6, c = e & 63;
        Ast[c][r] = A [(size_t)(i0 + r) * DIM + c];
        Bst[c][r] = Bp[(size_t)(j0 + r) * DIM + c];
    }
    __syncthreads();

    float acc[4][4] = {};
    #pragma unroll 16
    for (int k = 0; k < 64; k++) {
        float4 a4 = *(const float4*)&Ast[k][ty * 4];
        float4 b4 = *(const float4*)&Bst[k][tx * 4];
        float av[4] = {a4.x, a4.y, a4.z, a4.w};
        float bv[4] = {b4.x, b4.y, b4.z, b4.w};
        #pragma unroll
        for (int i = 0; i < 4; i++)
            #pragma unroll
            for (int j = 0; j < 4; j++)
                acc[i][j] = fmaf(av[i], bv[j], acc[i][j]);
    }

    const float scale = 0.125f;   // 1/sqrt(64)
    float rpart[4] = {};          // per-thread row partials (over its 4 j's)
    float cpart[4] = {};          // per-thread col partials (over its 4 i's)
    #pragma unroll
    for (int i = 0; i < 4; i++) {
        int gi = i0 + ty * 4 + i;
        #pragma unroll
        for (int j = 0; j < 4; j++) {
            float ev = fast_exp(acc[i][j] * scale);
            Eb[(size_t)gi * TOK + j0 + tx * 4 + j] = ev;
            rpart[i] += ev;
            cpart[j] += ev;
        }
    }

    // stage partials through the (now dead) smem tiles; stride 17 = conflict-free
    __syncthreads();                       // everyone done reading Ast/Bst
    float* rowbuf = &Ast[0][0];            // [64 rows][16 tx] stride 17
    float* colbuf = &Bst[0][0];            // [64 cols][16 ty] stride 17
    #pragma unroll
    for (int i = 0; i < 4; i++) rowbuf[(ty * 4 + i) * 17 + tx] = rpart[i];
    #pragma unroll
    for (int j = 0; j < 4; j++) colbuf[(tx * 4 + j) * 17 + ty] = cpart[j];
    __syncthreads();

    if (tid < 64) {
        float s = 0.f;
        #pragma unroll
        for (int t = 0; t < 16; t++) s += rowbuf[tid * 17 + t];
        atomicAdd(&rs[bh * TOK + i0 + tid], s);
    } else if (tid < 128) {
        int c = tid - 64;
        float s = 0.f;
        #pragma unroll
        for (int t = 0; t < 16; t++) s += colbuf[c * 17 + t];
        atomicAdd(&cs[bh * TOK + j0 + c], s);
    }
}

// ---------------- merged: m0 = (E @ v1)/rs  (z=0) | m1 = (E^T @ v0)/cs (z=1) ----------------
__global__ __launch_bounds__(256)
void apply_both(const float* __restrict__ E,
                const float* __restrict__ v0g, const float* __restrict__ v1g,
                const float* __restrict__ rs,  const float* __restrict__ cs,
                float* __restrict__ m0g, float* __restrict__ m1g)
{
    __shared__ float Pst[64][68];
    __shared__ float Vst[64][68];
    const int mode = blockIdx.z;            // 0 = row-softmax (m0), 1 = col-softmax (m1)
    const int i0 = blockIdx.x * 64;
    const int bh = blockIdx.y;
    const int b  = bh >> 2, h = bh & 3;
    const float* Eb  = E + (size_t)bh * TOK * TOK;
    const float* Vb  = (mode ? v0g : v1g) + (size_t)b * TOK * DIM + h * HDIM;
    const float* sum = (mode ? cs : rs) + bh * TOK;
    float* Mout      = (mode ? m1g : m0g);
    const int tid = threadIdx.x, ty = tid >> 4, tx = tid & 15;

    float acc[4][4] = {};
    for (int j0 = 0; j0 < TOK; j0 += 64) {
        for (int e = tid; e < 4096; e += 256) {
            int r = e >> 6, c = e & 63;
            if (mode == 0)
                Pst[c][r] = Eb[(size_t)(i0 + r) * TOK + j0 + c];
            else
                Pst[r][c] = Eb[(size_t)(j0 + r) * TOK + i0 + c];
            Vst[r][c] = Vb[(size_t)(j0 + r) * DIM + c];
        }
        __syncthreads();
        #pragma unroll 16
        for (int k = 0; k < 64; k++) {
            float4 a4 = *(const float4*)&Pst[k][ty * 4];
            float4 b4 = *(const float4*)&Vst[k][tx * 4];
            float av[4] = {a4.x, a4.y, a4.z, a4.w};
            float bv[4] = {b4.x, b4.y, b4.z, b4.w};
            #pragma unroll
            for (int i = 0; i < 4; i++)
                #pragma unroll
                for (int j = 0; j < 4; j++)
                    acc[i][j] = fmaf(av[i], bv[j], acc[i][j]);
        }
        __syncthreads();
    }
    #pragma unroll
    for (int i = 0; i < 4; i++) {
        int gi = i0 + ty * 4 + i;
        float s = 1.0f / sum[gi];
        #pragma unroll
        for (int j = 0; j < 4; j++)
            Mout[(size_t)(b * TOK + gi) * DIM + h * HDIM + tx * 4 + j] = acc[i][j] * s;
    }
}

// ---------------- fused LayerNorm + exact GELU, in-place on [rows, 512] ----------------
__global__ __launch_bounds__(256)
void ln_gelu(float* __restrict__ Y0, float* __restrict__ Y1,
             const float* __restrict__ gam, const float* __restrict__ bet)
{
    const int row = blockIdx.x;
    float* y = (blockIdx.y ? Y1 : Y0) + (size_t)row * 512;
    const int t = threadIdx.x;

    float v0 = y[t], v1 = y[t + 256];

    __shared__ float red[256];
    red[t] = v0 + v1;
    __syncthreads();
    for (int off = 128; off > 0; off >>= 1) {
        if (t < off) red[t] += red[t + off];
        __syncthreads();
    }
    float mu = red[0] * (1.0f / 512.0f);
    __syncthreads();

    float d0 = v0 - mu, d1 = v1 - mu;
    red[t] = d0 * d0 + d1 * d1;
    __syncthreads();
    for (int off = 128; off > 0; off >>= 1) {
        if (t < off) red[t] += red[t + off];
        __syncthreads();
    }
    float inv = rsqrtf(red[0] * (1.0f / 512.0f) + 1e-5f);

    float z0 = d0 * inv * gam[t] + bet[t];
    float z1 = d1 * inv * gam[t + 256] + bet[t + 256];
    y[t]       = 0.5f * z0 * (1.0f + erff(z0 * 0.70710678118654752f));
    y[t + 256] = 0.5f * z1 * (1.0f + erff(z1 * 0.70710678118654752f));
}

// ---------------- launch ----------------
extern "C" void kernel_launch(void* const* d_in, const int* in_sizes, int n_in,
                              void* d_out, int out_size)
{
    const float* x0   = (const float*)d_in[0];
    const float* x1   = (const float*)d_in[1];
    const float* Wqk  = (const float*)d_in[2];
    const float* bqk  = (const float*)d_in[3];
    const float* Wv   = (const float*)d_in[4];
    const float* bv   = (const float*)d_in[5];
    const float* Wout = (const float*)d_in[6];
    const float* bout = (const float*)d_in[7];
    const float* W0   = (const float*)d_in[8];
    const float* b0   = (const float*)d_in[9];
    const float* lns  = (const float*)d_in[10];
    const float* lnb  = (const float*)d_in[11];
    const float* W3   = (const float*)d_in[12];
    const float* b3   = (const float*)d_in[13];

    float* out0 = (float*)d_out;
    float* out1 = (float*)d_out + (size_t)MTOK * DIM;

    float *qk0, *qk1, *v0, *v1, *m0, *m1, *mp0, *mp1, *y0, *y1, *E, *rs, *cs;
    cudaGetSymbolAddress((void**)&qk0, g_qk0);
    cudaGetSymbolAddress((void**)&qk1, g_qk1);
    cudaGetSymbolAddress((void**)&v0,  g_v0);
    cudaGetSymbolAddress((void**)&v1,  g_v1);
    cudaGetSymbolAddress((void**)&m0,  g_m0);
    cudaGetSymbolAddress((void**)&m1,  g_m1);
    cudaGetSymbolAddress((void**)&mp0, g_mp0);
    cudaGetSymbolAddress((void**)&mp1, g_mp1);
    cudaGetSymbolAddress((void**)&y0,  g_y0);
    cudaGetSymbolAddress((void**)&y1,  g_y1);
    cudaGetSymbolAddress((void**)&E,   g_E);
    cudaGetSymbolAddress((void**)&rs,  g_rs);
    cudaGetSymbolAddress((void**)&cs,  g_cs);

    dim3 thr(256);

    // zero sum accumulators (must happen every replay)
    zero_sums<<<(BH * TOK + 511) / 512, 512>>>(rs, cs);

    // projections: 4 x [8192,256]@[256,256] in one launch (z selects)
    proj_kernel<<<dim3(MTOK / 64, DIM / 64, 4), thr>>>(
        x0, x1, Wqk, bqk, Wv, bv, qk0, qk1, v0, v1);

    // E = exp(scale * qk0 @ qk1^T) per (b,h), with fused row/col sums
    logits_exp<<<dim3(TOK / 64, TOK / 64, BH), thr>>>(qk0, qk1, E, rs, cs);

    // both attention applies in one launch (reciprocal fused in epilogue)
    apply_both<<<dim3(TOK / 64, BH, 2), thr>>>(E, v0, v1, rs, cs, m0, m1);

    // out projection (both streams)
    wout_kernel<<<dim3(MTOK / 64, DIM / 64, 2), thr>>>(m0, m1, Wout, bout, mp0, mp1);

    // FFN1: [x | m] @ W0 + b0 -> [8192, 512] (both streams)
    ffn1_kernel<<<dim3(MTOK / 64, 512 / 64, 2), thr>>>(x0, x1, mp0, mp1, W0, b0, y0, y1);

    // LN + GELU in place (both streams)
    ln_gelu<<<dim3(MTOK, 2), thr>>>(y0, y1, lns, lnb);

    // FFN2 + residual (both streams)
    ffn2_kernel<<<dim3(MTOK / 64, DIM / 64, 2), thr>>>(y0, y1, W3, b3, x0, x1, out0, out1);
}

// round 14
// speedup vs baseline: 1.2073x; 1.1521x over previous
#include <cuda_runtime.h>
#include <cuda_bf16.h>
#include <math.h>
#include <stdint.h>

// Problem constants
#define TOK   2048
#define DIM   256
#define HDIM  64
#define NH    4
#define NB    4
#define MTOK  8192        // NB*TOK
#define BH    16          // NB*NH

// ---------------- scratch (device globals; no allocation allowed) ----------------
__device__ float    g_qk0[MTOK * DIM];
__device__ float    g_qk1[MTOK * DIM];
__device__ float    g_v0 [MTOK * DIM];
__device__ float    g_v1 [MTOK * DIM];
__device__ float    g_m0 [MTOK * DIM];
__device__ float    g_m1 [MTOK * DIM];
__device__ float    g_mp0[MTOK * DIM];
__device__ float    g_mp1[MTOK * DIM];
__device__ float    g_y0 [MTOK * 512];
__device__ float    g_y1 [MTOK * 512];
__device__ uint32_t g_Epk [(size_t)BH * TOK * TOK];   // exp(logits) packed (bf16 hi | lo<<16)
__device__ uint32_t g_ETpk[(size_t)BH * TOK * TOK];   // transposed copy
__device__ uint32_t g_vt0 [(size_t)BH * HDIM * TOK];  // v0^T packed per (b,h): [64][2048]
__device__ uint32_t g_vt1 [(size_t)BH * HDIM * TOK];  // v1^T packed

// ---------------- helpers ----------------
__device__ __forceinline__ uint32_t smem_u32(const void* p) {
    uint32_t a;
    asm("{ .reg .u64 t; cvta.to.shared.u64 t, %1; cvt.u32.u64 %0, t; }" : "=r"(a) : "l"(p));
    return a;
}

// ldmatrix (sm_75+, portable to compute_103)
#define LDSM_X4(r, addr) \
    asm volatile("ldmatrix.sync.aligned.m8n8.x4.shared.b16 {%0,%1,%2,%3}, [%4];" \
        : "=r"((r)[0]), "=r"((r)[1]), "=r"((r)[2]), "=r"((r)[3]) : "r"(addr))
#define LDSM_X2(r, addr) \
    asm volatile("ldmatrix.sync.aligned.m8n8.x2.shared.b16 {%0,%1}, [%2];" \
        : "=r"((r)[0]), "=r"((r)[1]) : "r"(addr))

// mma.sync bf16 (sm_80+, portable to compute_103)
#define MMA16816(d, a, b) \
    asm volatile("mma.sync.aligned.m16n8k16.row.col.f32.bf16.bf16.f32 " \
        "{%0,%1,%2,%3}, {%4,%5,%6,%7}, {%8,%9}, {%0,%1,%2,%3};" \
        : "+f"((d)[0]), "+f"((d)[1]), "+f"((d)[2]), "+f"((d)[3]) \
        : "r"((a)[0]), "r"((a)[1]), "r"((a)[2]), "r"((a)[3]), "r"((b)[0]), "r"((b)[1]))

// pack/unpack (hi bf16 in low 16, lo bf16 in high 16)
__device__ __forceinline__ uint32_t pack_hl(float f) {
    __nv_bfloat16 h = __float2bfloat16(f);
    float hf = __bfloat162float(h);
    __nv_bfloat16 l = __float2bfloat16(f - hf);
    return (uint32_t)__bfloat16_as_ushort(h) | ((uint32_t)__bfloat16_as_ushort(l) << 16);
}
__device__ __forceinline__ float unpack_sum(uint32_t pk) {
    return __uint_as_float(pk << 16) + __uint_as_float(pk & 0xffff0000u);
}

// ---------------- fast exp on the FMA pipe ----------------
__device__ __forceinline__ float fast_exp(float x) {
    float t = x * 1.4426950408889634f;
    float r = rintf(t);
    float f = t - r;
    float p = 1.5403530e-4f;
    p = fmaf(p, f, 1.3333558e-3f);
    p = fmaf(p, f, 9.6181291e-3f);
    p = fmaf(p, f, 5.5504109e-2f);
    p = fmaf(p, f, 2.4022651e-1f);
    p = fmaf(p, f, 6.9314718e-1f);
    p = fmaf(p, f, 1.0f);
    int e = (int)r;
    return __int_as_float(__float_as_int(p) + (e << 23));
}

// ---------------- generic tiled fp32 GEMM core (validated) ----------------
template<bool CONCAT, bool RES>
__device__ __forceinline__
void gemm_core(const float* __restrict__ A, const float* __restrict__ A2,
               const float* __restrict__ W, const float* __restrict__ bias,
               const float* __restrict__ res, float* __restrict__ C,
               int N, int K)
{
    __shared__ float Ast[16][68];
    __shared__ float Wst[16][68];
    const int row0 = blockIdx.x * 64;
    const int col0 = blockIdx.y * 64;
    const int tid  = threadIdx.x;
    const int ty   = tid >> 4, tx = tid & 15;

    float acc[4][4] = {};

    for (int k0 = 0; k0 < K; k0 += 16) {
        #pragma unroll
        for (int e = tid; e < 1024; e += 256) {
            int r = e >> 4, c = e & 15;
            int kk = k0 + c;
            float v;
            if (CONCAT) {
                v = (kk < 256) ? A [(size_t)(row0 + r) * 256 + kk]
                               : A2[(size_t)(row0 + r) * 256 + (kk - 256)];
            } else {
                v = A[(size_t)(row0 + r) * K + kk];
            }
            Ast[c][r] = v;
        }
        #pragma unroll
        for (int e = tid; e < 1024; e += 256) {
            int kk = e >> 6, n = e & 63;
            Wst[kk][n] = W[(size_t)(k0 + kk) * N + col0 + n];
        }
        __syncthreads();
        #pragma unroll
        for (int kk = 0; kk < 16; kk++) {
            float4 a4 = *(const float4*)&Ast[kk][ty * 4];
            float4 b4 = *(const float4*)&Wst[kk][tx * 4];
            float av[4] = {a4.x, a4.y, a4.z, a4.w};
            float bv[4] = {b4.x, b4.y, b4.z, b4.w};
            #pragma unroll
            for (int i = 0; i < 4; i++)
                #pragma unroll
                for (int j = 0; j < 4; j++)
                    acc[i][j] = fmaf(av[i], bv[j], acc[i][j]);
        }
        __syncthreads();
    }

    #pragma unroll
    for (int i = 0; i < 4; i++) {
        int r = row0 + ty * 4 + i;
        #pragma unroll
        for (int j = 0; j < 4; j++) {
            int c = col0 + tx * 4 + j;
            float v = acc[i][j] + bias[c];
            if (RES) v += res[(size_t)r * N + c];
            C[(size_t)r * N + c] = v;
        }
    }
}

__global__ __launch_bounds__(256)
void proj_kernel(const float* __restrict__ x0, const float* __restrict__ x1,
                 const float* __restrict__ Wqk, const float* __restrict__ bqk,
                 const float* __restrict__ Wv,  const float* __restrict__ bv,
                 float* __restrict__ qk0, float* __restrict__ qk1,
                 float* __restrict__ v0,  float* __restrict__ v1)
{
    const int z = blockIdx.z;
    const float* A = (z & 1) ? x1 : x0;
    const float* W = (z < 2) ? Wqk : Wv;
    const float* b = (z < 2) ? bqk : bv;
    float* C = (z == 0) ? qk0 : (z == 1) ? qk1 : (z == 2) ? v0 : v1;
    gemm_core<false, false>(A, nullptr, W, b, nullptr, C, DIM, DIM);
}

__global__ __launch_bounds__(256)
void wout_kernel(const float* __restrict__ m0, const float* __restrict__ m1,
                 const float* __restrict__ Wout, const float* __restrict__ bout,
                 float* __restrict__ mp0, float* __restrict__ mp1)
{
    const int z = blockIdx.z;
    gemm_core<false, false>(z ? m1 : m0, nullptr, Wout, bout, nullptr,
                            z ? mp1 : mp0, DIM, DIM);
}

__global__ __launch_bounds__(256)
void ffn1_kernel(const float* __restrict__ x0, const float* __restrict__ x1,
                 const float* __restrict__ mp0, const float* __restrict__ mp1,
                 const float* __restrict__ W0, const float* __restrict__ b0,
                 float* __restrict__ y0, float* __restrict__ y1)
{
    const int z = blockIdx.z;
    gemm_core<true, false>(z ? x1 : x0, z ? mp1 : mp0, W0, b0, nullptr,
                           z ? y1 : y0, 512, 512);
}

__global__ __launch_bounds__(256)
void ffn2_kernel(const float* __restrict__ y0, const float* __restrict__ y1,
                 const float* __restrict__ W3, const float* __restrict__ b3,
                 const float* __restrict__ x0, const float* __restrict__ x1,
                 float* __restrict__ out0, float* __restrict__ out1)
{
    const int z = blockIdx.z;
    gemm_core<false, true>(z ? y1 : y0, nullptr, W3, b3, z ? x1 : x0,
                           z ? out1 : out0, DIM, 512);
}

// ---------------- v -> vT packed bf16(hi,lo) conversion ----------------
__global__ __launch_bounds__(256)
void vt_convert(const float* __restrict__ v0, const float* __restrict__ v1,
                uint32_t* __restrict__ vt0, uint32_t* __restrict__ vt1)
{
    __shared__ uint32_t sbuf[64][65];
    const int t0 = blockIdx.x * 64;
    const int bh = blockIdx.y;
    const int b  = bh >> 2, h = bh & 3;
    const float* src = blockIdx.z ? v1 : v0;
    uint32_t*    dst = blockIdx.z ? vt1 : vt0;
    const int tid = threadIdx.x;

    #pragma unroll
    for (int m = 0; m < 16; m++) {
        int e = tid + 256 * m;
        int tt = e >> 6, d = e & 63;
        float f = src[((size_t)b * TOK + t0 + tt) * DIM + h * HDIM + d];
        sbuf[tt][d] = pack_hl(f);
    }
    __syncthreads();
    #pragma unroll
    for (int m = 0; m < 16; m++) {
        int e = tid + 256 * m;
        int d = e >> 6, tt = e & 63;
        dst[((size_t)bh * HDIM + d) * TOK + t0 + tt] = sbuf[tt][d];
    }
}

// ---------------- logits (SIMT NT GEMM, K=64) + exp -> Epk and ETpk ----------------
__global__ __launch_bounds__(256)
void logits_exp(const float* __restrict__ qk0, const float* __restrict__ qk1,
                uint32_t* __restrict__ Epk, uint32_t* __restrict__ ETpk)
{
    __shared__ float Ast[64][68];   // [k][i]
    __shared__ float Bst[64][68];   // [k][j]
    const int i0 = blockIdx.x * 64;
    const int j0 = blockIdx.y * 64;
    const int bh = blockIdx.z;
    const int b  = bh >> 2, h = bh & 3;
    const float* A  = qk0 + (size_t)b * TOK * DIM + h * HDIM;
    const float* Bp = qk1 + (size_t)b * TOK * DIM + h * HDIM;
    uint32_t* Eb  = Epk  + (size_t)bh * TOK * TOK;
    uint32_t* ETb = ETpk + (size_t)bh * TOK * TOK;
    const int tid = threadIdx.x, ty = tid >> 4, tx = tid & 15;

    for (int e = tid; e < 4096; e += 256) {
        int r = e >> 6, c = e & 63;
        Ast[c][r] = A [(size_t)(i0 + r) * DIM + c];
        Bst[c][r] = Bp[(size_t)(j0 + r) * DIM + c];
    }
    __syncthreads();

    float acc[4][4] = {};
    #pragma unroll 16
    for (int k = 0; k < 64; k++) {
        float4 a4 = *(const float4*)&Ast[k][ty * 4];
        float4 b4 = *(const float4*)&Bst[k][tx * 4];
        float av[4] = {a4.x, a4.y, a4.z, a4.w};
        float bv[4] = {b4.x, b4.y, b4.z, b4.w};
        #pragma unroll
        for (int i = 0; i < 4; i++)
            #pragma unroll
            for (int j = 0; j < 4; j++)
                acc[i][j] = fmaf(av[i], bv[j], acc[i][j]);
    }

    // pack into smem tile (reuse Ast storage), then write E and ET coalesced
    __syncthreads();
    uint32_t (*tb)[68] = reinterpret_cast<uint32_t(*)[68]>(&Ast[0][0]);
    const float scale = 0.125f;
    #pragma unroll
    for (int i = 0; i < 4; i++) {
        uint32_t p0 = pack_hl(fast_exp(acc[i][0] * scale));
        uint32_t p1 = pack_hl(fast_exp(acc[i][1] * scale));
        uint32_t p2 = pack_hl(fast_exp(acc[i][2] * scale));
        uint32_t p3 = pack_hl(fast_exp(acc[i][3] * scale));
        uint4 q = {p0, p1, p2, p3};
        *(uint4*)&tb[ty * 4 + i][tx * 4] = q;
    }
    __syncthreads();

    #pragma unroll
    for (int m = 0; m < 16; m++) {
        int e = tid + 256 * m;
        int r = e >> 6, c = e & 63;
        Eb [(size_t)(i0 + r) * TOK + j0 + c] = tb[r][c];
        ETb[(size_t)(j0 + r) * TOK + i0 + c] = tb[c][r];
    }
}

// ---------------- mma.sync attention apply (bf16 split-precision) ----------------
// mode z=0: m0[i,d] = sum_j E[i,j] vT1[d,j] / rowsum
// mode z=1: m1[j,d] = sum_i ET[j,i] vT0[d,i] / rowsum(ET rows)
// smem planes, stride 36 u32 (144B) per row -> conflict-free stores + ldmatrix.
static constexpr int OFF_AH = 0;                       // 128 x 36 u32 = 18432 B
static constexpr int OFF_AL = 18432;                   // 18432
static constexpr int OFF_BH = 36864;                   // 64 x 36 u32 = 9216
static constexpr int OFF_BL = 46080;                   // 9216
static constexpr int OFF_RS = 55296;                   // 512
static constexpr int APL_SMEM = 55808;

__global__ __launch_bounds__(256)
void attn_apply_mma(const uint32_t* __restrict__ Epk, const uint32_t* __restrict__ ETpk,
                    const uint32_t* __restrict__ vt0, const uint32_t* __restrict__ vt1,
                    float* __restrict__ m0, float* __restrict__ m1)
{
    extern __shared__ char smem[];
    const uint32_t smem_base = smem_u32(smem);
    const int tid  = threadIdx.x;
    const int wid  = tid >> 5, lane = tid & 31;
    const int mode = blockIdx.z;
    const int i0   = blockIdx.x * 128;
    const int bh   = blockIdx.y;
    const int b    = bh >> 2, h = bh & 3;

    const uint32_t* Ab = (mode ? ETpk : Epk) + (size_t)bh * TOK * TOK;
    const uint32_t* Vb = (mode ? vt0 : vt1) + (size_t)bh * HDIM * TOK;
    float* Mout = mode ? m1 : m0;

    float acc[8][4];
    #pragma unroll
    for (int nt = 0; nt < 8; nt++)
        #pragma unroll
        for (int c = 0; c < 4; c++) acc[nt][c] = 0.f;

    float racc[16];
    #pragma unroll
    for (int m = 0; m < 16; m++) racc[m] = 0.f;

    const int R = wid * 16;   // this warp's output row base

    for (int kt = 0; kt < TOK; kt += 64) {
        // ---- stage A (128 rows x 64 k) as hi/lo bf16x2 planes ----
        #pragma unroll
        for (int m = 0; m < 16; m++) {
            int r = wid + 8 * m;
            uint2 u = ((const uint2*)(Ab + (size_t)(i0 + r) * TOK + kt))[lane];
            uint32_t hp = __byte_perm(u.x, u.y, 0x5410);
            uint32_t lp = __byte_perm(u.x, u.y, 0x7632);
            *(uint32_t*)(smem + OFF_AH + (r * 36 + lane) * 4) = hp;
            *(uint32_t*)(smem + OFF_AL + (r * 36 + lane) * 4) = lp;
            racc[m] += unpack_sum(u.x) + unpack_sum(u.y);
        }
        // ---- stage B (64 rows x 64 k) ----
        #pragma unroll
        for (int m = 0; m < 8; m++) {
            int r = wid + 8 * m;
            uint2 u = ((const uint2*)(Vb + (size_t)r * TOK + kt))[lane];
            uint32_t hp = __byte_perm(u.x, u.y, 0x5410);
            uint32_t lp = __byte_perm(u.x, u.y, 0x7632);
            *(uint32_t*)(smem + OFF_BH + (r * 36 + lane) * 4) = hp;
            *(uint32_t*)(smem + OFF_BL + (r * 36 + lane) * 4) = lp;
        }
        __syncthreads();

        // ---- compute: per warp 16x64 tile, 4 k-subs x 8 n-tiles x 3 mma ----
        #pragma unroll
        for (int ks = 0; ks < 4; ks++) {
            uint32_t aaddr = smem_base + OFF_AH +
                ((R + (lane & 15)) * 36 + ks * 8 + ((lane >> 4) << 2)) * 4;
            uint32_t ah[4], al[4];
            LDSM_X4(ah, aaddr);
            LDSM_X4(al, aaddr + (OFF_AL - OFF_AH));
            #pragma unroll
            for (int nt = 0; nt < 8; nt++) {
                uint32_t baddr = smem_base + OFF_BH +
                    ((nt * 8 + (lane & 7)) * 36 + ks * 8 + (((lane >> 3) & 1) << 2)) * 4;
                uint32_t bhf[2], blf[2];
                LDSM_X2(bhf, baddr);
                LDSM_X2(blf, baddr + (OFF_BL - OFF_BH));
                MMA16816(acc[nt], ah, bhf);
                MMA16816(acc[nt], ah, blf);
                MMA16816(acc[nt], al, bhf);
            }
        }
        __syncthreads();
    }

    // ---- row sums: warp wid staged rows wid + 8m ----
    float* rsum_s = (float*)(smem + OFF_RS);
    #pragma unroll
    for (int m = 0; m < 16; m++) {
        float v = racc[m];
        #pragma unroll
        for (int d = 16; d > 0; d >>= 1) v += __shfl_xor_sync(0xffffffffu, v, d);
        if (lane == 0) rsum_s[wid + 8 * m] = v;
    }
    __syncthreads();

    // ---- epilogue: fragment layout -> normalized output ----
    const int g = lane >> 2, tg = lane & 3;
    const float inv0 = 1.0f / rsum_s[R + g];
    const float inv1 = 1.0f / rsum_s[R + g + 8];
    float* out0p = Mout + ((size_t)b * TOK + i0 + R + g) * DIM + h * HDIM;
    float* out1p = out0p + 8 * DIM;
    #pragma unroll
    for (int nt = 0; nt < 8; nt++) {
        float2 o0 = {acc[nt][0] * inv0, acc[nt][1] * inv0};
        float2 o1 = {acc[nt][2] * inv1, acc[nt][3] * inv1};
        *(float2*)(out0p + nt * 8 + tg * 2) = o0;
        *(float2*)(out1p + nt * 8 + tg * 2) = o1;
    }
}

// ---------------- fused LayerNorm + exact GELU ----------------
__global__ __launch_bounds__(256)
void ln_gelu(float* __restrict__ Y0, float* __restrict__ Y1,
             const float* __restrict__ gam, const float* __restrict__ bet)
{
    const int row = blockIdx.x;
    float* y = (blockIdx.y ? Y1 : Y0) + (size_t)row * 512;
    const int t = threadIdx.x;

    float v0 = y[t], v1 = y[t + 256];

    __shared__ float red[256];
    red[t] = v0 + v1;
    __syncthreads();
    for (int off = 128; off > 0; off >>= 1) {
        if (t < off) red[t] += red[t + off];
        __syncthreads();
    }
    float mu = red[0] * (1.0f / 512.0f);
    __syncthreads();

    float d0 = v0 - mu, d1 = v1 - mu;
    red[t] = d0 * d0 + d1 * d1;
    __syncthreads();
    for (int off = 128; off > 0; off >>= 1) {
        if (t < off) red[t] += red[t + off];
        __syncthreads();
    }
    float inv = rsqrtf(red[0] * (1.0f / 512.0f) + 1e-5f);

    float z0 = d0 * inv * gam[t] + bet[t];
    float z1 = d1 * inv * gam[t + 256] + bet[t + 256];
    y[t]       = 0.5f * z0 * (1.0f + erff(z0 * 0.70710678118654752f));
    y[t + 256] = 0.5f * z1 * (1.0f + erff(z1 * 0.70710678118654752f));
}

// ---------------- launch ----------------
extern "C" void kernel_launch(void* const* d_in, const int* in_sizes, int n_in,
                              void* d_out, int out_size)
{
    const float* x0   = (const float*)d_in[0];
    const float* x1   = (const float*)d_in[1];
    const float* Wqk  = (const float*)d_in[2];
    const float* bqk  = (const float*)d_in[3];
    const float* Wv   = (const float*)d_in[4];
    const float* bv   = (const float*)d_in[5];
    const float* Wout = (const float*)d_in[6];
    const float* bout = (const float*)d_in[7];
    const float* W0   = (const float*)d_in[8];
    const float* b0   = (const float*)d_in[9];
    const float* lns  = (const float*)d_in[10];
    const float* lnb  = (const float*)d_in[11];
    const float* W3   = (const float*)d_in[12];
    const float* b3   = (const float*)d_in[13];

    float* out0 = (float*)d_out;
    float* out1 = (float*)d_out + (size_t)MTOK * DIM;

    float *qk0, *qk1, *v0, *v1, *m0, *m1, *mp0, *mp1, *y0, *y1;
    uint32_t *Epk, *ETpk, *vt0, *vt1;
    cudaGetSymbolAddress((void**)&qk0, g_qk0);
    cudaGetSymbolAddress((void**)&qk1, g_qk1);
    cudaGetSymbolAddress((void**)&v0,  g_v0);
    cudaGetSymbolAddress((void**)&v1,  g_v1);
    cudaGetSymbolAddress((void**)&m0,  g_m0);
    cudaGetSymbolAddress((void**)&m1,  g_m1);
    cudaGetSymbolAddress((void**)&mp0, g_mp0);
    cudaGetSymbolAddress((void**)&mp1, g_mp1);
    cudaGetSymbolAddress((void**)&y0,  g_y0);
    cudaGetSymbolAddress((void**)&y1,  g_y1);
    cudaGetSymbolAddress((void**)&Epk,  g_Epk);
    cudaGetSymbolAddress((void**)&ETpk, g_ETpk);
    cudaGetSymbolAddress((void**)&vt0,  g_vt0);
    cudaGetSymbolAddress((void**)&vt1,  g_vt1);

    cudaFuncSetAttribute(attn_apply_mma, cudaFuncAttributeMaxDynamicSharedMemorySize, APL_SMEM);

    dim3 thr(256);

    // projections
    proj_kernel<<<dim3(MTOK / 64, DIM / 64, 4), thr>>>(
        x0, x1, Wqk, bqk, Wv, bv, qk0, qk1, v0, v1);

    // v -> vT packed bf16(hi,lo)
    vt_convert<<<dim3(TOK / 64, BH, 2), thr>>>(v0, v1, vt0, vt1);

    // E = exp(scale * qk0 @ qk1^T) packed, plus transposed copy
    logits_exp<<<dim3(TOK / 64, TOK / 64, BH), thr>>>(qk0, qk1, Epk, ETpk);

    // tensor-core (mma.sync) attention apply, both directions
    attn_apply_mma<<<dim3(TOK / 128, BH, 2), thr, APL_SMEM>>>(Epk, ETpk, vt0, vt1, m0, m1);

    // out projection
    wout_kernel<<<dim3(MTOK / 64, DIM / 64, 2), thr>>>(m0, m1, Wout, bout, mp0, mp1);

    // FFN1
    ffn1_kernel<<<dim3(MTOK / 64, 512 / 64, 2), thr>>>(x0, x1, mp0, mp1, W0, b0, y0, y1);

    // LN + GELU
    ln_gelu<<<dim3(MTOK, 2), thr>>>(y0, y1, lns, lnb);

    // FFN2 + residual
    ffn2_kernel<<<dim3(MTOK / 64, DIM / 64, 2), thr>>>(y0, y1, W3, b3, x0, x1, out0, out1);
}